// round 2
// baseline (speedup 1.0000x reference)
#include <cuda_runtime.h>
#include <math.h>

#define NMAXC 50000
#define EMAXC 800000
#define HD 128
#define TT 4
#define EPSC 1e-5f
#define DTC 0.1f

// ----------------------------- scratch (static device globals; no allocs) ---
__device__ float  g_bufA[NMAXC * HD];
__device__ float  g_bufB[NMAXC * HD];
__device__ float  g_meshO[NMAXC * HD];
__device__ float  g_C0[NMAXC * HD];
__device__ float  g_tmp8[NMAXC * 8];
__device__ float  g_G[NMAXC * 4];
__device__ float  g_y4[NMAXC * 4];
__device__ float  g_Fp[NMAXC * 4];
__device__ int    g_deg[NMAXC];
__device__ float  g_dinv[NMAXC];
__device__ int    g_rowptr[NMAXC + 1];
__device__ int    g_cursor[NMAXC];
__device__ int    g_csrc[EMAXC];
__device__ float  g_cw[EMAXC];
__device__ double g_stats[256];
__device__ float  g_mean[HD];
__device__ float  g_rstd[HD];

// ----------------------------- helpers -------------------------------------
__device__ __forceinline__ float4 f4fma(float s, float4 a, float4 acc) {
    acc.x = fmaf(s, a.x, acc.x);
    acc.y = fmaf(s, a.y, acc.y);
    acc.z = fmaf(s, a.z, acc.z);
    acc.w = fmaf(s, a.w, acc.w);
    return acc;
}

// ----------------------------- CSR build -----------------------------------
__global__ void __launch_bounds__(256) k_init_deg(int n) {
    int i = blockIdx.x * blockDim.x + threadIdx.x;
    if (i < n) g_deg[i] = 1;  // self loop
}

__global__ void __launch_bounds__(256) k_count(const int* __restrict__ dst, int e) {
    int i = blockIdx.x * blockDim.x + threadIdx.x;
    if (i < e) atomicAdd(&g_deg[dst[i]], 1);
}

__global__ void __launch_bounds__(1024) k_scan(int n, int e) {
    __shared__ int sm[1024];
    int t = threadIdx.x;
    int chunk = (n + 1023) >> 10;
    int lo = t * chunk;
    int hi = min(n, lo + chunk);
    int s = 0;
    for (int i = lo; i < hi; i++) s += g_deg[i] - 1;
    sm[t] = s;
    __syncthreads();
    for (int off = 1; off < 1024; off <<= 1) {
        int v = (t >= off) ? sm[t - off] : 0;
        __syncthreads();
        sm[t] += v;
        __syncthreads();
    }
    int run = sm[t] - s;  // exclusive prefix
    for (int i = lo; i < hi; i++) {
        int c = g_deg[i] - 1;
        g_rowptr[i] = run;
        g_cursor[i] = run;
        g_dinv[i] = rsqrtf((float)g_deg[i]);
        run += c;
    }
    if (t == 0) g_rowptr[n] = e;
}

__global__ void __launch_bounds__(256) k_fill(const int* __restrict__ src,
                                              const int* __restrict__ dst, int e) {
    int i = blockIdx.x * blockDim.x + threadIdx.x;
    if (i >= e) return;
    int d = dst[i];
    int p = atomicAdd(&g_cursor[d], 1);
    int s = src[i];
    g_csrc[p] = s;
    g_cw[p] = g_dinv[s];
}

// ----------------------------- SpMM width 128 (warp per row) ----------------
__global__ void __launch_bounds__(256) k_spmm128(const float* __restrict__ h,
                                                 float* __restrict__ out,
                                                 const float* __restrict__ bias,
                                                 int n, int dotanh) {
    int gw = (blockIdx.x * blockDim.x + threadIdx.x) >> 5;
    int lane = threadIdx.x & 31;
    if (gw >= n) return;
    int beg = g_rowptr[gw], end = g_rowptr[gw + 1];
    float di = g_dinv[gw];
    const float4* hp = (const float4*)h;
    float4 sv = hp[(size_t)gw * 32 + lane];
    float4 acc = make_float4(di * sv.x, di * sv.y, di * sv.z, di * sv.w);
    int e2 = beg;
    for (; e2 + 4 <= end; e2 += 4) {
        int s0 = g_csrc[e2 + 0], s1 = g_csrc[e2 + 1];
        int s2 = g_csrc[e2 + 2], s3 = g_csrc[e2 + 3];
        float w0 = g_cw[e2 + 0], w1 = g_cw[e2 + 1];
        float w2 = g_cw[e2 + 2], w3 = g_cw[e2 + 3];
        float4 v0 = hp[(size_t)s0 * 32 + lane];
        float4 v1 = hp[(size_t)s1 * 32 + lane];
        float4 v2 = hp[(size_t)s2 * 32 + lane];
        float4 v3 = hp[(size_t)s3 * 32 + lane];
        acc = f4fma(w0, v0, acc);
        acc = f4fma(w1, v1, acc);
        acc = f4fma(w2, v2, acc);
        acc = f4fma(w3, v3, acc);
    }
    for (; e2 < end; e2++) {
        int s = g_csrc[e2];
        float w = g_cw[e2];
        acc = f4fma(w, hp[(size_t)s * 32 + lane], acc);
    }
    acc.x *= di; acc.y *= di; acc.z *= di; acc.w *= di;
    if (bias) {
        float4 b = ((const float4*)bias)[lane];
        acc.x += b.x; acc.y += b.y; acc.z += b.z; acc.w += b.w;
    }
    if (dotanh) {
        acc.x = tanhf(acc.x); acc.y = tanhf(acc.y);
        acc.z = tanhf(acc.z); acc.w = tanhf(acc.w);
    }
    ((float4*)out)[(size_t)gw * 32 + lane] = acc;
}

// ----------------------------- SpMM small widths (thread per row) -----------
template <int C4>
__global__ void __launch_bounds__(256) k_spmm_small(const float* __restrict__ x,
                                                    float* __restrict__ out, int n) {
    int r = blockIdx.x * blockDim.x + threadIdx.x;
    if (r >= n) return;
    int beg = g_rowptr[r], end = g_rowptr[r + 1];
    float di = g_dinv[r];
    const float4* xp = (const float4*)x;
    float4 acc[C4];
#pragma unroll
    for (int j = 0; j < C4; j++) {
        float4 s = xp[(size_t)r * C4 + j];
        acc[j] = make_float4(di * s.x, di * s.y, di * s.z, di * s.w);
    }
    for (int e2 = beg; e2 < end; e2++) {
        int s = g_csrc[e2];
        float w = g_cw[e2];
#pragma unroll
        for (int j = 0; j < C4; j++) acc[j] = f4fma(w, xp[(size_t)s * C4 + j], acc[j]);
    }
#pragma unroll
    for (int j = 0; j < C4; j++) {
        acc[j].x *= di; acc[j].y *= di; acc[j].z *= di; acc[j].w *= di;
        ((float4*)out)[(size_t)r * C4 + j] = acc[j];
    }
}

// Final width-4 SpMM + timestep update (tanh, Euler step, output write)
__global__ void __launch_bounds__(256) k_spmm4_final(const float* __restrict__ y,
                                                     const float* __restrict__ bias,
                                                     float* __restrict__ Fprev,
                                                     float* __restrict__ out,
                                                     float* __restrict__ outd,
                                                     int n, int t) {
    int r = blockIdx.x * blockDim.x + threadIdx.x;
    if (r >= n) return;
    int beg = g_rowptr[r], end = g_rowptr[r + 1];
    float di = g_dinv[r];
    const float4* yp = (const float4*)y;
    float4 sv = yp[r];
    float4 acc = make_float4(di * sv.x, di * sv.y, di * sv.z, di * sv.w);
    for (int e2 = beg; e2 < end; e2++) {
        int s = g_csrc[e2];
        float w = g_cw[e2];
        acc = f4fma(w, yp[s], acc);
    }
    float4 b = ((const float4*)bias)[0];
    acc.x = acc.x * di + b.x;
    acc.y = acc.y * di + b.y;
    acc.z = acc.z * di + b.z;
    acc.w = acc.w * di + b.w;
    float4 fd = make_float4(tanhf(acc.x), tanhf(acc.y), tanhf(acc.z), tanhf(acc.w));
    float4 fp = ((const float4*)Fprev)[r];
    float4 fn = make_float4(tanhf(fmaf(DTC, fd.x, fp.x)),
                            tanhf(fmaf(DTC, fd.y, fp.y)),
                            tanhf(fmaf(DTC, fd.z, fp.z)),
                            tanhf(fmaf(DTC, fd.w, fp.w)));
    ((float4*)Fprev)[r] = fn;
    ((float4*)out)[(size_t)r * TT + t] = fn;    // Fs  [N,T,4]
    ((float4*)outd)[(size_t)r * TT + t] = fd;   // Fds [N,T,4]
}

// ----------------------------- GEMM K=128, Ncols=128 ------------------------
// C[64-row tile] = op(A) @ W (+bias). op: 0 none, 1 relu, 2 (a-m)*rstd then relu
__global__ void __launch_bounds__(256) k_gemm128(const float* __restrict__ A,
                                                 const float* __restrict__ W,
                                                 float* __restrict__ C,
                                                 const float* __restrict__ bias,
                                                 int n, int op) {
    __shared__ float As[32 * 65];
    __shared__ float Ws[32 * 128];
    int tid = threadIdx.x;
    int r0 = blockIdx.x * 64;
    int rowg = tid >> 5;   // 0..7
    int colg = tid & 31;   // 0..31
    float4 acc[8];
#pragma unroll
    for (int i = 0; i < 8; i++) acc[i] = make_float4(0.f, 0.f, 0.f, 0.f);

    for (int k0 = 0; k0 < 128; k0 += 32) {
#pragma unroll
        for (int j = 0; j < 8; j++) {
            int lin = tid + j * 256;          // 0..2047 over 64 rows x 32 k
            int row = lin >> 5, kk = lin & 31;
            int gr = r0 + row;
            float v = (gr < n) ? A[(size_t)gr * 128 + k0 + kk] : 0.f;
            if (op == 2) v = (v - g_mean[k0 + kk]) * g_rstd[k0 + kk];
            if (op >= 1) v = fmaxf(v, 0.f);
            As[kk * 65 + row] = v;
        }
#pragma unroll
        for (int j = 0; j < 4; j++) {
            int lin = tid + j * 256;          // over 1024 float4 = 32 k x 32 col4
            int kk = lin >> 5, c4 = lin & 31;
            ((float4*)Ws)[kk * 32 + c4] = ((const float4*)W)[(size_t)(k0 + kk) * 32 + c4];
        }
        __syncthreads();
#pragma unroll
        for (int kk = 0; kk < 32; kk++) {
            float4 w = ((const float4*)Ws)[kk * 32 + colg];
#pragma unroll
            for (int i = 0; i < 8; i++) {
                float a = As[kk * 65 + rowg * 8 + i];
                acc[i] = f4fma(a, w, acc[i]);
            }
        }
        __syncthreads();
    }
    float4 b = bias ? ((const float4*)bias)[colg] : make_float4(0.f, 0.f, 0.f, 0.f);
#pragma unroll
    for (int i = 0; i < 8; i++) {
        int gr = r0 + rowg * 8 + i;
        if (gr < n) {
            float4 o = acc[i];
            o.x += b.x; o.y += b.y; o.z += b.z; o.w += b.w;
            ((float4*)C)[(size_t)gr * 32 + colg] = o;
        }
    }
}

// ----------------------------- GEMM small K (warp per row), 128 out cols ----
template <int K, bool ADDBUF>
__global__ void __launch_bounds__(256) k_gemmK(const float* __restrict__ A,
                                               const float* __restrict__ W,
                                               const float* __restrict__ bias,
                                               const float* __restrict__ addbuf,
                                               float* __restrict__ C, int n) {
    __shared__ float4 Ws[K * 32];
    int tid = threadIdx.x;
    for (int i = tid; i < K * 32; i += blockDim.x) Ws[i] = ((const float4*)W)[i];
    __syncthreads();
    int r = (blockIdx.x * blockDim.x + tid) >> 5;
    int lane = tid & 31;
    if (r >= n) return;
    float a[K];
#pragma unroll
    for (int k = 0; k < K; k++) a[k] = A[(size_t)r * K + k];
    float4 acc;
    if (ADDBUF) acc = ((const float4*)addbuf)[(size_t)r * 32 + lane];
    else if (bias) acc = ((const float4*)bias)[lane];
    else acc = make_float4(0.f, 0.f, 0.f, 0.f);
#pragma unroll
    for (int k = 0; k < K; k++) acc = f4fma(a[k], Ws[k * 32 + lane], acc);
    ((float4*)C)[(size_t)r * 32 + lane] = acc;
}

// ----------------------------- GEMM K=128 -> 4 out cols (thread per row) ----
__global__ void __launch_bounds__(256) k_gemmN4(const float* __restrict__ A,
                                                const float* __restrict__ W,
                                                float* __restrict__ out, int n) {
    __shared__ float4 Ws[128];
    int tid = threadIdx.x;
    for (int i = tid; i < 128; i += blockDim.x) Ws[i] = ((const float4*)W)[i];
    __syncthreads();
    int r = blockIdx.x * blockDim.x + tid;
    if (r >= n) return;
    const float4* ar = (const float4*)(A + (size_t)r * 128);
    float4 acc = make_float4(0.f, 0.f, 0.f, 0.f);
#pragma unroll
    for (int k4 = 0; k4 < 32; k4++) {
        float4 a = ar[k4];
        float4 w0 = Ws[4 * k4 + 0], w1 = Ws[4 * k4 + 1];
        float4 w2 = Ws[4 * k4 + 2], w3 = Ws[4 * k4 + 3];
        acc = f4fma(a.x, w0, acc);
        acc = f4fma(a.y, w1, acc);
        acc = f4fma(a.z, w2, acc);
        acc = f4fma(a.w, w3, acc);
    }
    ((float4*)out)[r] = acc;
}

// ----------------------------- instance-norm stats --------------------------
__global__ void __launch_bounds__(256) k_zero_stats() { g_stats[threadIdx.x] = 0.0; }

__global__ void __launch_bounds__(128) k_stats(const float* __restrict__ x, int n) {
    int c = threadIdx.x;  // 128 threads, one column each
    double s = 0.0, s2 = 0.0;
    for (int r = blockIdx.x; r < n; r += gridDim.x) {
        float v = x[(size_t)r * 128 + c];
        s += v;
        s2 += (double)v * (double)v;
    }
    atomicAdd(&g_stats[c], s);
    atomicAdd(&g_stats[128 + c], s2);
}

__global__ void __launch_bounds__(128) k_finalize(int n) {
    int c = threadIdx.x;
    double m = g_stats[c] / n;
    double v = g_stats[128 + c] / n - m * m;
    g_mean[c] = (float)m;
    g_rstd[c] = rsqrtf((float)v + EPSC);
}

// ----------------------------- host orchestration ---------------------------
extern "C" void kernel_launch(void* const* d_in, const int* in_sizes, int n_in,
                              void* d_out, int out_size) {
    const float* F0    = (const float*)d_in[0];
    const float* meshf = (const float*)d_in[1];
    const int*   ei    = (const int*)d_in[2];
    int n = in_sizes[0] / 4;          // F_0 is [N,1,4]
    if (in_sizes[1] / 8 != n) n = in_sizes[1] / 8;  // cross-check vs meshfield [N,8]
    int e = in_sizes[2] / 2;
    // weight base index: skip the scalar n_time input if it sits at slot 3
    int b = 3;
    if (n_in >= 16 && in_sizes[3] <= 4) b = 4;
    const float* mW0 = (const float*)d_in[b + 0];
    const float* mb0 = (const float*)d_in[b + 1];
    const float* mWm = (const float*)d_in[b + 2];
    const float* mbm = (const float*)d_in[b + 3];
    const float* mWl = (const float*)d_in[b + 4];
    const float* mbl = (const float*)d_in[b + 5];
    const float* dW0 = (const float*)d_in[b + 6];
    const float* db0 = (const float*)d_in[b + 7];
    const float* dWm = (const float*)d_in[b + 8];
    const float* dbm = (const float*)d_in[b + 9];
    const float* dWl = (const float*)d_in[b + 10];
    const float* dbl = (const float*)d_in[b + 11];

    float *bufA, *bufB, *meshO, *C0, *tmp8, *G, *y4, *Fp;
    cudaGetSymbolAddress((void**)&bufA, g_bufA);
    cudaGetSymbolAddress((void**)&bufB, g_bufB);
    cudaGetSymbolAddress((void**)&meshO, g_meshO);
    cudaGetSymbolAddress((void**)&C0, g_C0);
    cudaGetSymbolAddress((void**)&tmp8, g_tmp8);
    cudaGetSymbolAddress((void**)&G, g_G);
    cudaGetSymbolAddress((void**)&y4, g_y4);
    cudaGetSymbolAddress((void**)&Fp, g_Fp);

    const int* src = ei;
    const int* dst = ei + e;
    int gN256 = (n + 255) / 256;
    int gE256 = (e + 255) / 256;
    int gW    = (n + 7) / 8;      // warp-per-row, 8 warps per 256-thread block
    int gT64  = (n + 63) / 64;    // gemm128 64-row tiles

    // --- CSR + symmetric normalization (graph fixed; rebuilt each replay) ---
    k_init_deg<<<gN256, 256>>>(n);
    k_count<<<gE256, 256>>>(dst, e);
    k_scan<<<1, 1024>>>(n, e);
    k_fill<<<gE256, 256>>>(src, dst, e);

    // --- mesh block ---
    k_spmm_small<2><<<gN256, 256>>>(meshf, tmp8, n);              // A^ * meshfield (width 8)
    k_gemmK<8, false><<<gW, 256>>>(tmp8, mW0, mb0, nullptr, bufA, n);
    k_zero_stats<<<1, 256>>>();
    k_stats<<<256, 128>>>(bufA, n);
    k_finalize<<<1, 128>>>(n);
    for (int i = 0; i < 8; i++) {
        k_gemm128<<<gT64, 256>>>(bufA, mWm + (size_t)i * HD * HD, bufB, nullptr, n, i == 0 ? 2 : 1);
        k_spmm128<<<gW, 256>>>(bufB, bufA, mbm + (size_t)i * HD, n, 0);
    }
    k_gemm128<<<gT64, 256>>>(bufA, mWl, bufB, nullptr, n, 0);
    k_spmm128<<<gW, 256>>>(bufB, meshO, mbl, n, 1);               // tanh -> mesh

    // --- time-invariant precompute: C0 = (A^ mesh) @ dW0[4:] + db0 ---
    k_spmm128<<<gW, 256>>>(meshO, bufB, nullptr, n, 0);           // A^ * mesh
    k_gemm128<<<gT64, 256>>>(bufB, dW0 + 4 * HD, C0, db0, n, 0);

    cudaMemcpyAsync(Fp, F0, (size_t)n * 4 * sizeof(float), cudaMemcpyDeviceToDevice, 0);

    float* out  = (float*)d_out;
    float* outd = out + (size_t)out_size / 2;   // Fds half of the output
    for (int t = 0; t < TT; t++) {
        k_spmm_small<1><<<gN256, 256>>>(Fp, G, n);                // A^ * F_prev (width 4)
        k_gemmK<4, true><<<gW, 256>>>(G, dW0, nullptr, C0, bufA, n);  // + C0 (holds db0)
        k_zero_stats<<<1, 256>>>();
        k_stats<<<256, 128>>>(bufA, n);
        k_finalize<<<1, 128>>>(n);
        for (int i = 0; i < 8; i++) {
            k_gemm128<<<gT64, 256>>>(bufA, dWm + (size_t)i * HD * HD, bufB, nullptr, n, i == 0 ? 2 : 1);
            k_spmm128<<<gW, 256>>>(bufB, bufA, dbm + (size_t)i * HD, n, 0);
        }
        k_gemmN4<<<gN256, 256>>>(bufA, dWl, y4, n);               // [N,128]@[128,4]
        k_spmm4_final<<<gN256, 256>>>(y4, dbl, Fp, out, outd, n, t);
    }
}